// round 13
// baseline (speedup 1.0000x reference)
#include <cuda_runtime.h>
#include <cuda_bf16.h>
#include <math.h>
#include <stdint.h>

#define NUM_ITEMS 10000
#define EMBED 64
#define BATCH 32
#define MAX_HIST 200
#define LEAKY 0.2f
#define SHIFT 64.0f
#define GCHUNK 25

#define TILE_M 256            // items per CTA
#define ROWB 144              // padded row stride bytes (72 bf16)
#define ROWE 72               // elements per padded row
#define BT_ELEMS (MAX_HIST * ROWE)          // 14400 bf16 per tile
#define BT_BYTES (BT_ELEMS * 2)             // 28800
#define B_BYTES (4 * BT_BYTES)              // 115200
#define E_BYTES (TILE_M * ROWB)             // 36864 per (hi|lo)
#define SM_ELO  E_BYTES
#define SM_B    (2 * E_BYTES)               // 73728
#define SM_TOTAL (SM_B + B_BYTES)           // 188928

typedef unsigned long long u64;

// ---------------- scratch (__device__ globals; no allocs) ----------------
__device__ float g_h[BATCH * MAX_HIST * EMBED];   // gathered hist fp32
__device__ float g_whbar[BATCH * EMBED];          // W @ hbar
__device__ __align__(16) __nv_bfloat16 g_split[BATCH][4 * BT_ELEMS];

// mma.sync m16n8k16 row.col f32.bf16.bf16.f32 (sm_80+; valid on plain sm_100)
#define MMA16816(d, a, b)                                                   \
    asm volatile("mma.sync.aligned.m16n8k16.row.col.f32.bf16.bf16.f32 "     \
        "{%0,%1,%2,%3}, {%4,%5,%6,%7}, {%8,%9}, {%0,%1,%2,%3};"             \
        : "+f"((d)[0]), "+f"((d)[1]), "+f"((d)[2]), "+f"((d)[3])            \
        : "r"((a)[0]), "r"((a)[1]), "r"((a)[2]), "r"((a)[3]),               \
          "r"((b)[0]), "r"((b)[1]))

// ---------------------------------------------------------------------------
// prep_gather: grid (8, BATCH), 512 threads. Gather 25 hist rows -> g_h
// fp32, compute wh = W@h, split both to bf16 hi/lo into padded g_split.
// ---------------------------------------------------------------------------
__global__ __launch_bounds__(512)
void prep_gather_kernel(const int* __restrict__ ids,
                        const float* __restrict__ E,
                        const float* __restrict__ W) {
    __shared__ float s_Wt[EMBED * EMBED];   // s_Wt[j*64+f] = W[f][j]
    __shared__ float s_h[GCHUNK * EMBED];
    __shared__ float s_w[GCHUNK * EMBED];
    int b = blockIdx.y;
    int base = blockIdx.x * GCHUNK;
    int tid = threadIdx.x;
    __nv_bfloat16* sp = g_split[b];

    for (int k = tid; k < EMBED * EMBED; k += 512) {
        int f = k >> 6;
        int j = k & 63;
        s_Wt[j * EMBED + f] = W[k];
    }
    float* hb = g_h + (size_t)b * MAX_HIST * EMBED;
    for (int idx = tid; idx < GCHUNK * EMBED; idx += 512) {
        int nl = idx >> 6;
        int f = idx & 63;
        float v = E[(size_t)ids[b * MAX_HIST + base + nl] * EMBED + f];
        s_h[idx] = v;
        hb[(base + nl) * EMBED + f] = v;
    }
    __syncthreads();

    for (int idx = tid; idx < GCHUNK * EMBED; idx += 512) {
        int nl = idx >> 6;
        int f = idx & 63;
        const float* h = s_h + nl * EMBED;
        float a0 = 0.f, a1 = 0.f, a2 = 0.f, a3 = 0.f;
#pragma unroll
        for (int j = 0; j < EMBED; j += 4) {
            a0 = fmaf(s_Wt[(j + 0) * EMBED + f], h[j + 0], a0);
            a1 = fmaf(s_Wt[(j + 1) * EMBED + f], h[j + 1], a1);
            a2 = fmaf(s_Wt[(j + 2) * EMBED + f], h[j + 2], a2);
            a3 = fmaf(s_Wt[(j + 3) * EMBED + f], h[j + 3], a3);
        }
        s_w[idx] = (a0 + a1) + (a2 + a3);
    }
    __syncthreads();

    for (int idx = tid; idx < GCHUNK * EMBED; idx += 512) {
        int nl = idx >> 6;
        int f = idx & 63;
        int n = base + nl;
        int o = n * ROWE + f;
        float hv = s_h[idx];
        __nv_bfloat16 hh = __float2bfloat16(hv);
        __nv_bfloat16 hl = __float2bfloat16(hv - __bfloat162float(hh));
        sp[0 * BT_ELEMS + o] = hh;
        sp[1 * BT_ELEMS + o] = hl;
        float wv = s_w[idx];
        __nv_bfloat16 wh = __float2bfloat16(wv);
        __nv_bfloat16 wl = __float2bfloat16(wv - __bfloat162float(wh));
        sp[2 * BT_ELEMS + o] = wh;
        sp[3 * BT_ELEMS + o] = wl;
    }
}

// ---------------------------------------------------------------------------
// prep_soft: per batch — user softmax, parallel hbar, whbar = W@hbar.
// ---------------------------------------------------------------------------
__global__ __launch_bounds__(256)
void prep_soft_kernel(const int* __restrict__ lens,
                      const float* __restrict__ U,
                      const float* __restrict__ W) {
    __shared__ float s_u[EMBED];
    __shared__ float s_red[256];
    __shared__ float s_p[256];
    __shared__ float s_hbar[EMBED];
    int b = blockIdx.x;
    int tid = threadIdx.x;
    int len = lens[b];
    const float* hb = g_h + (size_t)b * MAX_HIST * EMBED;

    if (tid < EMBED) s_u[tid] = U[tid];
    __syncthreads();

    float la = -1e30f;
    if (tid < len) {
        const float4* h4 = (const float4*)(hb + tid * EMBED);
        float a0 = 0.f, a1 = 0.f, a2 = 0.f, a3 = 0.f;
#pragma unroll
        for (int k = 0; k < 16; k += 4) {
            float4 v0 = h4[k], v1 = h4[k + 1], v2 = h4[k + 2], v3 = h4[k + 3];
            a0 = fmaf(s_u[4*k+0], v0.x, a0); a0 = fmaf(s_u[4*k+1], v0.y, a0);
            a0 = fmaf(s_u[4*k+2], v0.z, a0); a0 = fmaf(s_u[4*k+3], v0.w, a0);
            a1 = fmaf(s_u[4*k+4], v1.x, a1); a1 = fmaf(s_u[4*k+5], v1.y, a1);
            a1 = fmaf(s_u[4*k+6], v1.z, a1); a1 = fmaf(s_u[4*k+7], v1.w, a1);
            a2 = fmaf(s_u[4*k+8], v2.x, a2); a2 = fmaf(s_u[4*k+9], v2.y, a2);
            a2 = fmaf(s_u[4*k+10], v2.z, a2); a2 = fmaf(s_u[4*k+11], v2.w, a2);
            a3 = fmaf(s_u[4*k+12], v3.x, a3); a3 = fmaf(s_u[4*k+13], v3.y, a3);
            a3 = fmaf(s_u[4*k+14], v3.z, a3); a3 = fmaf(s_u[4*k+15], v3.w, a3);
        }
        float a = (a0 + a1) + (a2 + a3);
        la = (a > 0.f) ? a : LEAKY * a;
    }
    s_red[tid] = la;
    __syncthreads();
#pragma unroll
    for (int off = 128; off; off >>= 1) {
        if (tid < off) s_red[tid] = fmaxf(s_red[tid], s_red[tid + off]);
        __syncthreads();
    }
    float m = s_red[0];
    __syncthreads();
    float ev = (tid < len) ? __expf(la - m) : 0.f;
    s_red[tid] = ev;
    __syncthreads();
#pragma unroll
    for (int off = 128; off; off >>= 1) {
        if (tid < off) s_red[tid] += s_red[tid + off];
        __syncthreads();
    }
    float Z = s_red[0];
    __syncthreads();
    s_p[tid] = ev / Z;
    __syncthreads();

    {
        int c = tid >> 6;
        int f = tid & 63;
        int chunk = (len + 3) >> 2;
        int n0 = c * chunk;
        int n1 = min(len, n0 + chunk);
        float acc = 0.f;
        for (int n = n0; n < n1; n++)
            acc = fmaf(s_p[n], hb[n * EMBED + f], acc);
        s_red[tid] = acc;
    }
    __syncthreads();
    if (tid < EMBED)
        s_hbar[tid] = ((s_red[tid] + s_red[64 + tid]) +
                       (s_red[128 + tid] + s_red[192 + tid]));
    __syncthreads();

    if (tid < EMBED) {
        const float* wr = W + tid * EMBED;
        float a0 = 0.f, a1 = 0.f, a2 = 0.f, a3 = 0.f;
#pragma unroll
        for (int j = 0; j < EMBED; j += 4) {
            a0 = fmaf(wr[j + 0], s_hbar[j + 0], a0);
            a1 = fmaf(wr[j + 1], s_hbar[j + 1], a1);
            a2 = fmaf(wr[j + 2], s_hbar[j + 2], a2);
            a3 = fmaf(wr[j + 3], s_hbar[j + 3], a3);
        }
        g_whbar[b * EMBED + tid] = (a0 + a1) + (a2 + a3);
    }
}

// ---------------------------------------------------------------------------
// main: grid (40, BATCH), 256 threads (8 warps). Each warp owns 32 rows
// (2 m-tiles) — B fragments loaded ONCE per warp-n-tile feed 48 MMAs
// (2 m-tiles x 24), halving LDS volume vs 16-warp layout and deepening
// the tensor-pipe issue stream.
// ---------------------------------------------------------------------------
__global__ __launch_bounds__(256, 1)
void main_kernel(const float* __restrict__ E,
                 const int* __restrict__ lens,
                 const float* __restrict__ bias,
                 float* __restrict__ out) {
    extern __shared__ char smem[];
    int tid = threadIdx.x;
    int b = blockIdx.y;
    int i0 = blockIdx.x * TILE_M;
    int len = lens[b];

    // stage B tiles (contiguous copy, 115200 B)
    {
        const float4* src = (const float4*)(g_split[b]);
        float4* dst = (float4*)(smem + SM_B);
        for (int k = tid; k < B_BYTES / 16; k += 256) dst[k] = src[k];
    }
    // stage E tile as bf16 hi/lo with ROWB stride
    for (int idx = tid; idx < TILE_M * EMBED; idx += 256) {
        int m = idx >> 6;
        int f = idx & 63;
        int i = i0 + m;
        float v = (i < NUM_ITEMS) ? E[(size_t)i * EMBED + f] : 0.f;
        __nv_bfloat16 hi = __float2bfloat16(v);
        __nv_bfloat16 lo = __float2bfloat16(v - __bfloat162float(hi));
        *(__nv_bfloat16*)(smem + m * ROWB + f * 2) = hi;
        *(__nv_bfloat16*)(smem + SM_ELO + m * ROWB + f * 2) = lo;
    }
    __syncthreads();

    int wid = tid >> 5;     // 0..7
    int lane = tid & 31;
    int gr = lane >> 2;     // 0..7
    int tc = lane & 3;      // 0..3

    // preload A fragments for the warp's 2 m-tiles (hi/lo), 4 ks x 4 regs
    uint32_t aHi[2][4][4], aLo[2][4][4];
#pragma unroll
    for (int mt = 0; mt < 2; mt++) {
        int mbase = wid * 32 + mt * 16;
#pragma unroll
        for (int ks = 0; ks < 4; ks++) {
            int o = (mbase + gr) * ROWB + tc * 4 + ks * 32;
            aHi[mt][ks][0] = *(const uint32_t*)(smem + o);
            aHi[mt][ks][1] = *(const uint32_t*)(smem + o + 8 * ROWB);
            aHi[mt][ks][2] = *(const uint32_t*)(smem + o + 16);
            aHi[mt][ks][3] = *(const uint32_t*)(smem + o + 8 * ROWB + 16);
            aLo[mt][ks][0] = *(const uint32_t*)(smem + SM_ELO + o);
            aLo[mt][ks][1] = *(const uint32_t*)(smem + SM_ELO + o + 8 * ROWB);
            aLo[mt][ks][2] = *(const uint32_t*)(smem + SM_ELO + o + 16);
            aLo[mt][ks][3] = *(const uint32_t*)(smem + SM_ELO + o + 8 * ROWB + 16);
        }
    }

    const char* Bh  = smem + SM_B;                 // h_hi
    const char* Bhl = Bh + BT_BYTES;               // h_lo
    const char* Bw  = Bh + 2 * BT_BYTES;           // wh_hi
    const char* Bwl = Bh + 3 * BT_BYTES;           // wh_lo

    // accumulators per m-tile, per row group (gr, gr+8)
    float Z[2][2] = {{0.f, 0.f}, {0.f, 0.f}};
    float A[2][2] = {{0.f, 0.f}, {0.f, 0.f}};
    int nt = (len + 7) >> 3;

    for (int t = 0; t < nt; t++) {
        int rowb = (t * 8 + gr) * ROWB + tc * 4;
        uint32_t bH[4][2], bHl[4][2], bW[4][2], bWl[4][2];
#pragma unroll
        for (int ks = 0; ks < 4; ks++) {
            int o = rowb + ks * 32;
            bH[ks][0]  = *(const uint32_t*)(Bh + o);
            bH[ks][1]  = *(const uint32_t*)(Bh + o + 16);
            bHl[ks][0] = *(const uint32_t*)(Bhl + o);
            bHl[ks][1] = *(const uint32_t*)(Bhl + o + 16);
            bW[ks][0]  = *(const uint32_t*)(Bw + o);
            bW[ks][1]  = *(const uint32_t*)(Bw + o + 16);
            bWl[ks][0] = *(const uint32_t*)(Bwl + o);
            bWl[ks][1] = *(const uint32_t*)(Bwl + o + 16);
        }
        int n0 = t * 8 + tc * 2;
        int n1 = n0 + 1;
#pragma unroll
        for (int mt = 0; mt < 2; mt++) {
            float dA[4] = {0.f, 0.f, 0.f, 0.f};
            float dS[4] = {0.f, 0.f, 0.f, 0.f};
#pragma unroll
            for (int ks = 0; ks < 4; ks++) MMA16816(dA, aHi[mt][ks], bH[ks]);
#pragma unroll
            for (int ks = 0; ks < 4; ks++) MMA16816(dA, aHi[mt][ks], bHl[ks]);
#pragma unroll
            for (int ks = 0; ks < 4; ks++) MMA16816(dA, aLo[mt][ks], bH[ks]);
#pragma unroll
            for (int ks = 0; ks < 4; ks++) MMA16816(dS, aHi[mt][ks], bW[ks]);
#pragma unroll
            for (int ks = 0; ks < 4; ks++) MMA16816(dS, aHi[mt][ks], bWl[ks]);
#pragma unroll
            for (int ks = 0; ks < 4; ks++) MMA16816(dS, aLo[mt][ks], bW[ks]);

            {
                float a = dA[0], s = dS[0];
                float l = fmaxf(a, LEAKY * a);
                float tt = (n0 < len) ? __expf(fmaxf(l - SHIFT, -80.f)) : 0.f;
                Z[mt][0] += tt; A[mt][0] = fmaf(tt, s, A[mt][0]);
            }
            {
                float a = dA[1], s = dS[1];
                float l = fmaxf(a, LEAKY * a);
                float tt = (n1 < len) ? __expf(fmaxf(l - SHIFT, -80.f)) : 0.f;
                Z[mt][0] += tt; A[mt][0] = fmaf(tt, s, A[mt][0]);
            }
            {
                float a = dA[2], s = dS[2];
                float l = fmaxf(a, LEAKY * a);
                float tt = (n0 < len) ? __expf(fmaxf(l - SHIFT, -80.f)) : 0.f;
                Z[mt][1] += tt; A[mt][1] = fmaf(tt, s, A[mt][1]);
            }
            {
                float a = dA[3], s = dS[3];
                float l = fmaxf(a, LEAKY * a);
                float tt = (n1 < len) ? __expf(fmaxf(l - SHIFT, -80.f)) : 0.f;
                Z[mt][1] += tt; A[mt][1] = fmaf(tt, s, A[mt][1]);
            }
        }
    }

    // reduce across the 4 lanes of each row group, then write
#pragma unroll
    for (int mt = 0; mt < 2; mt++) {
#pragma unroll
        for (int half = 0; half < 2; half++) {
            float z = Z[mt][half], a = A[mt][half];
            z += __shfl_xor_sync(0xffffffffu, z, 1);
            z += __shfl_xor_sync(0xffffffffu, z, 2);
            a += __shfl_xor_sync(0xffffffffu, a, 1);
            a += __shfl_xor_sync(0xffffffffu, a, 2);
            if (tc == 0) {
                int i = i0 + wid * 32 + mt * 16 + gr + half * 8;
                if (i < NUM_ITEMS) {
                    const float4* er = (const float4*)(E + (size_t)i * EMBED);
                    const float4* wr = (const float4*)(g_whbar + b * EMBED);
                    const float4* br = (const float4*)bias;
                    float ub = 0.f, cb = 0.f;
#pragma unroll
                    for (int k = 0; k < 16; k++) {
                        float4 e = er[k], w = wr[k], bv = br[k];
                        ub = fmaf(e.x, w.x, ub); ub = fmaf(e.y, w.y, ub);
                        ub = fmaf(e.z, w.z, ub); ub = fmaf(e.w, w.w, ub);
                        cb = fmaf(e.x, bv.x, cb); cb = fmaf(e.y, bv.y, cb);
                        cb = fmaf(e.z, bv.z, cb); cb = fmaf(e.w, bv.w, cb);
                    }
                    out[b * NUM_ITEMS + i] = 0.5f * (a / z) + 0.5f * ub + cb;
                }
            }
        }
    }
}

// ---------------------------------------------------------------------------
extern "C" void kernel_launch(void* const* d_in, const int* in_sizes, int n_in,
                              void* d_out, int out_size) {
    const int*   ids  = (const int*)d_in[0];    // [32,200] int32
    const int*   lens = (const int*)d_in[1];    // [32] int32
    const float* E    = (const float*)d_in[2];  // [10000,64]
    const float* U    = (const float*)d_in[3];  // [1,64]
    const float* W    = (const float*)d_in[4];  // [64,64]
    const float* bias = (const float*)d_in[5];  // [64]
    float* out = (float*)d_out;                 // [32,10000]

    prep_gather_kernel<<<dim3(8, BATCH), 512>>>(ids, E, W);
    prep_soft_kernel<<<BATCH, 256>>>(lens, U, W);

    cudaFuncSetAttribute(main_kernel,
                         cudaFuncAttributeMaxDynamicSharedMemorySize, SM_TOTAL);
    dim3 grid((NUM_ITEMS + TILE_M - 1) / TILE_M, BATCH);
    main_kernel<<<grid, 256, SM_TOTAL>>>(E, lens, bias, out);
}

// round 14
// speedup vs baseline: 1.1334x; 1.1334x over previous
#include <cuda_runtime.h>
#include <cuda_fp16.h>
#include <math.h>
#include <stdint.h>

#define NUM_ITEMS 10000
#define EMBED 64
#define BATCH 32
#define MAX_HIST 200
#define LEAKY 0.2f
#define SHIFT 64.0f
#define GCHUNK 8

#define TILE_M 256            // items per CTA
#define ROWB 144              // padded row stride bytes (72 fp16)
#define ROWE 72               // elements per padded row
#define BT_ELEMS (MAX_HIST * ROWE)          // 14400 fp16 per tile
#define BT_BYTES (BT_ELEMS * 2)             // 28800
#define B_BYTES (4 * BT_BYTES)              // 115200
#define E_BYTES (TILE_M * ROWB)             // 36864 per (hi|lo)
#define SM_ELO  E_BYTES
#define SM_B    (2 * E_BYTES)               // 73728
#define SM_TOTAL (SM_B + B_BYTES)           // 188928

// ---------------- scratch (__device__ globals; no allocs) ----------------
__device__ float g_h[BATCH * MAX_HIST * EMBED];   // gathered hist fp32
__device__ float g_whbar[BATCH * EMBED];          // W @ hbar
// per batch, 4 contiguous padded fp16 tiles: h_hi, h_lo, wh_hi, wh_lo
__device__ __align__(16) __half g_split[BATCH][4 * BT_ELEMS];

// mma.sync m16n8k16 row.col f32.f16.f16.f32 (sm_80+; valid on plain sm_100)
#define MMA16816(d, a, b)                                                   \
    asm volatile("mma.sync.aligned.m16n8k16.row.col.f32.f16.f16.f32 "       \
        "{%0,%1,%2,%3}, {%4,%5,%6,%7}, {%8,%9}, {%0,%1,%2,%3};"             \
        : "+f"((d)[0]), "+f"((d)[1]), "+f"((d)[2]), "+f"((d)[3])            \
        : "r"((a)[0]), "r"((a)[1]), "r"((a)[2]), "r"((a)[3]),               \
          "r"((b)[0]), "r"((b)[1]))

// ---------------------------------------------------------------------------
// prep_gather: grid (25, BATCH), 256 threads. Gather 8 hist rows -> g_h
// fp32, compute wh = W@h, split both to fp16 hi/lo into padded g_split.
// Fine chunking (800 CTAs) hides the gather latency.
// ---------------------------------------------------------------------------
__global__ __launch_bounds__(256)
void prep_gather_kernel(const int* __restrict__ ids,
                        const float* __restrict__ E,
                        const float* __restrict__ W) {
    __shared__ float s_Wt[EMBED * EMBED];   // s_Wt[j*64+f] = W[f][j]
    __shared__ float s_h[GCHUNK * EMBED];
    __shared__ float s_w[GCHUNK * EMBED];
    int b = blockIdx.y;
    int base = blockIdx.x * GCHUNK;
    int tid = threadIdx.x;
    __half* sp = g_split[b];

    for (int k = tid; k < EMBED * EMBED; k += 256) {
        int f = k >> 6;
        int j = k & 63;
        s_Wt[j * EMBED + f] = W[k];
    }
    float* hb = g_h + (size_t)b * MAX_HIST * EMBED;
    for (int idx = tid; idx < GCHUNK * EMBED; idx += 256) {
        int nl = idx >> 6;
        int f = idx & 63;
        float v = E[(size_t)ids[b * MAX_HIST + base + nl] * EMBED + f];
        s_h[idx] = v;
        hb[(base + nl) * EMBED + f] = v;
    }
    __syncthreads();

    for (int idx = tid; idx < GCHUNK * EMBED; idx += 256) {
        int nl = idx >> 6;
        int f = idx & 63;
        const float* h = s_h + nl * EMBED;
        float a0 = 0.f, a1 = 0.f, a2 = 0.f, a3 = 0.f;
#pragma unroll
        for (int j = 0; j < EMBED; j += 4) {
            a0 = fmaf(s_Wt[(j + 0) * EMBED + f], h[j + 0], a0);
            a1 = fmaf(s_Wt[(j + 1) * EMBED + f], h[j + 1], a1);
            a2 = fmaf(s_Wt[(j + 2) * EMBED + f], h[j + 2], a2);
            a3 = fmaf(s_Wt[(j + 3) * EMBED + f], h[j + 3], a3);
        }
        s_w[idx] = (a0 + a1) + (a2 + a3);
    }
    __syncthreads();

    for (int idx = tid; idx < GCHUNK * EMBED; idx += 256) {
        int nl = idx >> 6;
        int f = idx & 63;
        int n = base + nl;
        int o = n * ROWE + f;
        float hv = s_h[idx];
        __half hh = __float2half_rn(hv);
        __half hl = __float2half_rn(hv - __half2float(hh));
        sp[0 * BT_ELEMS + o] = hh;
        sp[1 * BT_ELEMS + o] = hl;
        float wv = s_w[idx];
        __half wh = __float2half_rn(wv);
        __half wl = __float2half_rn(wv - __half2float(wh));
        sp[2 * BT_ELEMS + o] = wh;
        sp[3 * BT_ELEMS + o] = wl;
    }
}

// ---------------------------------------------------------------------------
// prep_soft: per batch — user softmax, parallel hbar, whbar = W@hbar.
// ---------------------------------------------------------------------------
__global__ __launch_bounds__(256)
void prep_soft_kernel(const int* __restrict__ lens,
                      const float* __restrict__ U,
                      const float* __restrict__ W) {
    __shared__ float s_u[EMBED];
    __shared__ float s_red[256];
    __shared__ float s_p[256];
    __shared__ float s_hbar[EMBED];
    int b = blockIdx.x;
    int tid = threadIdx.x;
    int len = lens[b];
    const float* hb = g_h + (size_t)b * MAX_HIST * EMBED;

    if (tid < EMBED) s_u[tid] = U[tid];
    __syncthreads();

    float la = -1e30f;
    if (tid < len) {
        const float4* h4 = (const float4*)(hb + tid * EMBED);
        float a0 = 0.f, a1 = 0.f, a2 = 0.f, a3 = 0.f;
#pragma unroll
        for (int k = 0; k < 16; k += 4) {
            float4 v0 = h4[k], v1 = h4[k + 1], v2 = h4[k + 2], v3 = h4[k + 3];
            a0 = fmaf(s_u[4*k+0], v0.x, a0); a0 = fmaf(s_u[4*k+1], v0.y, a0);
            a0 = fmaf(s_u[4*k+2], v0.z, a0); a0 = fmaf(s_u[4*k+3], v0.w, a0);
            a1 = fmaf(s_u[4*k+4], v1.x, a1); a1 = fmaf(s_u[4*k+5], v1.y, a1);
            a1 = fmaf(s_u[4*k+6], v1.z, a1); a1 = fmaf(s_u[4*k+7], v1.w, a1);
            a2 = fmaf(s_u[4*k+8], v2.x, a2); a2 = fmaf(s_u[4*k+9], v2.y, a2);
            a2 = fmaf(s_u[4*k+10], v2.z, a2); a2 = fmaf(s_u[4*k+11], v2.w, a2);
            a3 = fmaf(s_u[4*k+12], v3.x, a3); a3 = fmaf(s_u[4*k+13], v3.y, a3);
            a3 = fmaf(s_u[4*k+14], v3.z, a3); a3 = fmaf(s_u[4*k+15], v3.w, a3);
        }
        float a = (a0 + a1) + (a2 + a3);
        la = (a > 0.f) ? a : LEAKY * a;
    }
    s_red[tid] = la;
    __syncthreads();
#pragma unroll
    for (int off = 128; off; off >>= 1) {
        if (tid < off) s_red[tid] = fmaxf(s_red[tid], s_red[tid + off]);
        __syncthreads();
    }
    float m = s_red[0];
    __syncthreads();
    float ev = (tid < len) ? __expf(la - m) : 0.f;
    s_red[tid] = ev;
    __syncthreads();
#pragma unroll
    for (int off = 128; off; off >>= 1) {
        if (tid < off) s_red[tid] += s_red[tid + off];
        __syncthreads();
    }
    float Z = s_red[0];
    __syncthreads();
    s_p[tid] = ev / Z;
    __syncthreads();

    {
        int c = tid >> 6;
        int f = tid & 63;
        int chunk = (len + 3) >> 2;
        int n0 = c * chunk;
        int n1 = min(len, n0 + chunk);
        float acc = 0.f;
        for (int n = n0; n < n1; n++)
            acc = fmaf(s_p[n], hb[n * EMBED + f], acc);
        s_red[tid] = acc;
    }
    __syncthreads();
    if (tid < EMBED)
        s_hbar[tid] = ((s_red[tid] + s_red[64 + tid]) +
                       (s_red[128 + tid] + s_red[192 + tid]));
    __syncthreads();

    if (tid < EMBED) {
        const float* wr = W + tid * EMBED;
        float a0 = 0.f, a1 = 0.f, a2 = 0.f, a3 = 0.f;
#pragma unroll
        for (int j = 0; j < EMBED; j += 4) {
            a0 = fmaf(wr[j + 0], s_hbar[j + 0], a0);
            a1 = fmaf(wr[j + 1], s_hbar[j + 1], a1);
            a2 = fmaf(wr[j + 2], s_hbar[j + 2], a2);
            a3 = fmaf(wr[j + 3], s_hbar[j + 3], a3);
        }
        g_whbar[b * EMBED + tid] = (a0 + a1) + (a2 + a3);
    }
}

// ---------------------------------------------------------------------------
// main: grid (40, BATCH), 512 threads (16 warps) — the R12 winner layout.
// fp16 splits: logits 3-product (Ehi.Hhi + Ehi.Hlo + Elo.Hhi, 12 MMAs),
// scores 2-product (Ehi.Whi + Ehi.Wlo, 8 MMAs). 20 MMAs/n-tile vs 24.
// ---------------------------------------------------------------------------
__global__ __launch_bounds__(512, 1)
void main_kernel(const float* __restrict__ E,
                 const int* __restrict__ lens,
                 const float* __restrict__ bias,
                 float* __restrict__ out) {
    extern __shared__ char smem[];
    int tid = threadIdx.x;
    int b = blockIdx.y;
    int i0 = blockIdx.x * TILE_M;
    int len = lens[b];

    // stage B tiles (contiguous copy, 115200 B)
    {
        const float4* src = (const float4*)(g_split[b]);
        float4* dst = (float4*)(smem + SM_B);
        for (int k = tid; k < B_BYTES / 16; k += 512) dst[k] = src[k];
    }
    // stage E tile as fp16 hi/lo with ROWB stride
    for (int idx = tid; idx < TILE_M * EMBED; idx += 512) {
        int m = idx >> 6;
        int f = idx & 63;
        int i = i0 + m;
        float v = (i < NUM_ITEMS) ? E[(size_t)i * EMBED + f] : 0.f;
        __half hi = __float2half_rn(v);
        __half lo = __float2half_rn(v - __half2float(hi));
        *(__half*)(smem + m * ROWB + f * 2) = hi;
        *(__half*)(smem + SM_ELO + m * ROWB + f * 2) = lo;
    }
    __syncthreads();

    int wid = tid >> 5;
    int lane = tid & 31;
    int gr = lane >> 2;     // 0..7
    int tc = lane & 3;      // 0..3
    int mbase = wid * 16;

    // preload A fragments (E_hi, E_lo), 4 k-steps x 4 regs each
    uint32_t aHi[4][4], aLo[4][4];
#pragma unroll
    for (int ks = 0; ks < 4; ks++) {
        int o = (mbase + gr) * ROWB + tc * 4 + ks * 32;
        aHi[ks][0] = *(const uint32_t*)(smem + o);
        aHi[ks][1] = *(const uint32_t*)(smem + o + 8 * ROWB);
        aHi[ks][2] = *(const uint32_t*)(smem + o + 16);
        aHi[ks][3] = *(const uint32_t*)(smem + o + 8 * ROWB + 16);
        aLo[ks][0] = *(const uint32_t*)(smem + SM_ELO + o);
        aLo[ks][1] = *(const uint32_t*)(smem + SM_ELO + o + 8 * ROWB);
        aLo[ks][2] = *(const uint32_t*)(smem + SM_ELO + o + 16);
        aLo[ks][3] = *(const uint32_t*)(smem + SM_ELO + o + 8 * ROWB + 16);
    }

    const char* Bh  = smem + SM_B;                 // h_hi
    const char* Bhl = Bh + BT_BYTES;               // h_lo
    const char* Bw  = Bh + 2 * BT_BYTES;           // wh_hi
    const char* Bwl = Bh + 3 * BT_BYTES;           // wh_lo

    float Z0 = 0.f, Z1 = 0.f, A0 = 0.f, A1 = 0.f;  // rows gr, gr+8
    int nt = (len + 7) >> 3;

    for (int t = 0; t < nt; t++) {
        int rowb = (t * 8 + gr) * ROWB + tc * 4;
        uint32_t bH[4][2], bHl[4][2], bW[4][2], bWl[4][2];
#pragma unroll
        for (int ks = 0; ks < 4; ks++) {
            int o = rowb + ks * 32;
            bH[ks][0]  = *(const uint32_t*)(Bh + o);
            bH[ks][1]  = *(const uint32_t*)(Bh + o + 16);
            bHl[ks][0] = *(const uint32_t*)(Bhl + o);
            bHl[ks][1] = *(const uint32_t*)(Bhl + o + 16);
            bW[ks][0]  = *(const uint32_t*)(Bw + o);
            bW[ks][1]  = *(const uint32_t*)(Bw + o + 16);
            bWl[ks][0] = *(const uint32_t*)(Bwl + o);
            bWl[ks][1] = *(const uint32_t*)(Bwl + o + 16);
        }
        float dA[4] = {0.f, 0.f, 0.f, 0.f};
        float dS[4] = {0.f, 0.f, 0.f, 0.f};
        // logits: 3-product fp16
#pragma unroll
        for (int ks = 0; ks < 4; ks++) MMA16816(dA, aHi[ks], bH[ks]);
#pragma unroll
        for (int ks = 0; ks < 4; ks++) MMA16816(dA, aHi[ks], bHl[ks]);
#pragma unroll
        for (int ks = 0; ks < 4; ks++) MMA16816(dA, aLo[ks], bH[ks]);
        // scores: 2-product fp16 (Elo term dropped; ~1e-4 norm rel err)
#pragma unroll
        for (int ks = 0; ks < 4; ks++) MMA16816(dS, aHi[ks], bW[ks]);
#pragma unroll
        for (int ks = 0; ks < 4; ks++) MMA16816(dS, aHi[ks], bWl[ks]);

        int n0 = t * 8 + tc * 2;
        int n1 = n0 + 1;
        {
            float a = dA[0], s = dS[0];
            float l = fmaxf(a, LEAKY * a);
            float tt = (n0 < len) ? __expf(fmaxf(l - SHIFT, -80.f)) : 0.f;
            Z0 += tt; A0 = fmaf(tt, s, A0);
        }
        {
            float a = dA[1], s = dS[1];
            float l = fmaxf(a, LEAKY * a);
            float tt = (n1 < len) ? __expf(fmaxf(l - SHIFT, -80.f)) : 0.f;
            Z0 += tt; A0 = fmaf(tt, s, A0);
        }
        {
            float a = dA[2], s = dS[2];
            float l = fmaxf(a, LEAKY * a);
            float tt = (n0 < len) ? __expf(fmaxf(l - SHIFT, -80.f)) : 0.f;
            Z1 += tt; A1 = fmaf(tt, s, A1);
        }
        {
            float a = dA[3], s = dS[3];
            float l = fmaxf(a, LEAKY * a);
            float tt = (n1 < len) ? __expf(fmaxf(l - SHIFT, -80.f)) : 0.f;
            Z1 += tt; A1 = fmaf(tt, s, A1);
        }
    }

    // reduce across the 4 lanes of each row group (lane = gr*4 + tc)
    Z0 += __shfl_xor_sync(0xffffffffu, Z0, 1);
    Z0 += __shfl_xor_sync(0xffffffffu, Z0, 2);
    A0 += __shfl_xor_sync(0xffffffffu, A0, 1);
    A0 += __shfl_xor_sync(0xffffffffu, A0, 2);
    Z1 += __shfl_xor_sync(0xffffffffu, Z1, 1);
    Z1 += __shfl_xor_sync(0xffffffffu, Z1, 2);
    A1 += __shfl_xor_sync(0xffffffffu, A1, 1);
    A1 += __shfl_xor_sync(0xffffffffu, A1, 2);

    if (tc == 0) {
#pragma unroll
        for (int half = 0; half < 2; half++) {
            int i = i0 + mbase + gr + half * 8;
            if (i < NUM_ITEMS) {
                const float4* er = (const float4*)(E + (size_t)i * EMBED);
                const float4* wr = (const float4*)(g_whbar + b * EMBED);
                const float4* br = (const float4*)bias;
                float ub = 0.f, cb = 0.f;
#pragma unroll
                for (int k = 0; k < 16; k++) {
                    float4 e = er[k], w = wr[k], bv = br[k];
                    ub = fmaf(e.x, w.x, ub); ub = fmaf(e.y, w.y, ub);
                    ub = fmaf(e.z, w.z, ub); ub = fmaf(e.w, w.w, ub);
                    cb = fmaf(e.x, bv.x, cb); cb = fmaf(e.y, bv.y, cb);
                    cb = fmaf(e.z, bv.z, cb); cb = fmaf(e.w, bv.w, cb);
                }
                float Z = half ? Z1 : Z0;
                float A = half ? A1 : A0;
                out[b * NUM_ITEMS + i] = 0.5f * (A / Z) + 0.5f * ub + cb;
            }
        }
    }
}

// ---------------------------------------------------------------------------
extern "C" void kernel_launch(void* const* d_in, const int* in_sizes, int n_in,
                              void* d_out, int out_size) {
    const int*   ids  = (const int*)d_in[0];    // [32,200] int32
    const int*   lens = (const int*)d_in[1];    // [32] int32
    const float* E    = (const float*)d_in[2];  // [10000,64]
    const float* U    = (const float*)d_in[3];  // [1,64]
    const float* W    = (const float*)d_in[4];  // [64,64]
    const float* bias = (const float*)d_in[5];  // [64]
    float* out = (float*)d_out;                 // [32,10000]

    prep_gather_kernel<<<dim3(MAX_HIST / GCHUNK, BATCH), 256>>>(ids, E, W);
    prep_soft_kernel<<<BATCH, 256>>>(lens, U, W);

    cudaFuncSetAttribute(main_kernel,
                         cudaFuncAttributeMaxDynamicSharedMemorySize, SM_TOTAL);
    dim3 grid((NUM_ITEMS + TILE_M - 1) / TILE_M, BATCH);
    main_kernel<<<grid, 512, SM_TOTAL>>>(E, lens, bias, out);
}

// round 15
// speedup vs baseline: 1.2930x; 1.1408x over previous
#include <cuda_runtime.h>
#include <cuda_fp16.h>
#include <math.h>
#include <stdint.h>

#define NUM_ITEMS 10000
#define EMBED 64
#define BATCH 32
#define MAX_HIST 200
#define LEAKY 0.2f
#define SHIFT 64.0f
#define GCHUNK 25

#define TILE_M 256            // items per CTA
#define ROWB 144              // padded row stride bytes (72 fp16)
#define ROWE 72               // elements per padded row
#define BT_ELEMS (MAX_HIST * ROWE)          // 14400 fp16 per tile
#define BT_BYTES (BT_ELEMS * 2)             // 28800
#define B_BYTES (3 * BT_BYTES)              // 86400 (h_hi, h_lo, wh_hi)
#define E_BYTES (TILE_M * ROWB)             // 36864 per (hi|lo)
#define SM_ELO  E_BYTES
#define SM_B    (2 * E_BYTES)               // 73728
#define SM_TOTAL (SM_B + B_BYTES)           // 160128

// ---------------- scratch (__device__ globals; no allocs) ----------------
__device__ float g_h[BATCH * MAX_HIST * EMBED];   // gathered hist fp32
__device__ float g_whbar[BATCH * EMBED];          // W @ hbar
// per batch, 3 contiguous padded fp16 tiles: h_hi, h_lo, wh_hi
__device__ __align__(16) __half g_split[BATCH][3 * BT_ELEMS];

// mma.sync m16n8k16 row.col f32.f16.f16.f32 (sm_80+; valid on plain sm_100)
#define MMA16816(d, a, b)                                                   \
    asm volatile("mma.sync.aligned.m16n8k16.row.col.f32.f16.f16.f32 "       \
        "{%0,%1,%2,%3}, {%4,%5,%6,%7}, {%8,%9}, {%0,%1,%2,%3};"             \
        : "+f"((d)[0]), "+f"((d)[1]), "+f"((d)[2]), "+f"((d)[3])            \
        : "r"((a)[0]), "r"((a)[1]), "r"((a)[2]), "r"((a)[3]),               \
          "r"((b)[0]), "r"((b)[1]))

// ---------------------------------------------------------------------------
// prep_gather: grid (8, BATCH), 256 threads, 25 rows per CTA (W amortized).
// Gather hist -> g_h fp32, compute wh = W@h, split to fp16: h hi/lo, wh hi.
// ---------------------------------------------------------------------------
__global__ __launch_bounds__(256)
void prep_gather_kernel(const int* __restrict__ ids,
                        const float* __restrict__ E,
                        const float* __restrict__ W) {
    __shared__ float s_Wt[EMBED * EMBED];   // s_Wt[j*64+f] = W[f][j]
    __shared__ float s_h[GCHUNK * EMBED];
    int b = blockIdx.y;
    int base = blockIdx.x * GCHUNK;
    int tid = threadIdx.x;
    __half* sp = g_split[b];

    for (int k = tid; k < EMBED * EMBED; k += 256) {
        int f = k >> 6;
        int j = k & 63;
        s_Wt[j * EMBED + f] = W[k];
    }
    float* hb = g_h + (size_t)b * MAX_HIST * EMBED;
    for (int idx = tid; idx < GCHUNK * EMBED; idx += 256) {
        int nl = idx >> 6;
        int f = idx & 63;
        float v = E[(size_t)ids[b * MAX_HIST + base + nl] * EMBED + f];
        s_h[idx] = v;
        hb[(base + nl) * EMBED + f] = v;
        // split h while it's in registers
        int o = (base + nl) * ROWE + f;
        __half hh = __float2half_rn(v);
        sp[0 * BT_ELEMS + o] = hh;
        sp[1 * BT_ELEMS + o] = __float2half_rn(v - __half2float(hh));
    }
    __syncthreads();

    // wh[n][f] = sum_j W[f][j]*h[n][j]; store hi half only
    for (int idx = tid; idx < GCHUNK * EMBED; idx += 256) {
        int nl = idx >> 6;
        int f = idx & 63;
        const float* h = s_h + nl * EMBED;
        float a0 = 0.f, a1 = 0.f, a2 = 0.f, a3 = 0.f;
#pragma unroll
        for (int j = 0; j < EMBED; j += 4) {
            a0 = fmaf(s_Wt[(j + 0) * EMBED + f], h[j + 0], a0);
            a1 = fmaf(s_Wt[(j + 1) * EMBED + f], h[j + 1], a1);
            a2 = fmaf(s_Wt[(j + 2) * EMBED + f], h[j + 2], a2);
            a3 = fmaf(s_Wt[(j + 3) * EMBED + f], h[j + 3], a3);
        }
        float wv = (a0 + a1) + (a2 + a3);
        sp[2 * BT_ELEMS + (base + nl) * ROWE + f] = __float2half_rn(wv);
    }
}

// ---------------------------------------------------------------------------
// prep_soft: per batch — user softmax, parallel hbar, whbar = W@hbar.
// ---------------------------------------------------------------------------
__global__ __launch_bounds__(256)
void prep_soft_kernel(const int* __restrict__ lens,
                      const float* __restrict__ U,
                      const float* __restrict__ W) {
    __shared__ float s_u[EMBED];
    __shared__ float s_red[256];
    __shared__ float s_p[256];
    __shared__ float s_hbar[EMBED];
    int b = blockIdx.x;
    int tid = threadIdx.x;
    int len = lens[b];
    const float* hb = g_h + (size_t)b * MAX_HIST * EMBED;

    if (tid < EMBED) s_u[tid] = U[tid];
    __syncthreads();

    float la = -1e30f;
    if (tid < len) {
        const float4* h4 = (const float4*)(hb + tid * EMBED);
        float a0 = 0.f, a1 = 0.f, a2 = 0.f, a3 = 0.f;
#pragma unroll
        for (int k = 0; k < 16; k += 4) {
            float4 v0 = h4[k], v1 = h4[k + 1], v2 = h4[k + 2], v3 = h4[k + 3];
            a0 = fmaf(s_u[4*k+0], v0.x, a0); a0 = fmaf(s_u[4*k+1], v0.y, a0);
            a0 = fmaf(s_u[4*k+2], v0.z, a0); a0 = fmaf(s_u[4*k+3], v0.w, a0);
            a1 = fmaf(s_u[4*k+4], v1.x, a1); a1 = fmaf(s_u[4*k+5], v1.y, a1);
            a1 = fmaf(s_u[4*k+6], v1.z, a1); a1 = fmaf(s_u[4*k+7], v1.w, a1);
            a2 = fmaf(s_u[4*k+8], v2.x, a2); a2 = fmaf(s_u[4*k+9], v2.y, a2);
            a2 = fmaf(s_u[4*k+10], v2.z, a2); a2 = fmaf(s_u[4*k+11], v2.w, a2);
            a3 = fmaf(s_u[4*k+12], v3.x, a3); a3 = fmaf(s_u[4*k+13], v3.y, a3);
            a3 = fmaf(s_u[4*k+14], v3.z, a3); a3 = fmaf(s_u[4*k+15], v3.w, a3);
        }
        float a = (a0 + a1) + (a2 + a3);
        la = (a > 0.f) ? a : LEAKY * a;
    }
    s_red[tid] = la;
    __syncthreads();
#pragma unroll
    for (int off = 128; off; off >>= 1) {
        if (tid < off) s_red[tid] = fmaxf(s_red[tid], s_red[tid + off]);
        __syncthreads();
    }
    float m = s_red[0];
    __syncthreads();
    float ev = (tid < len) ? __expf(la - m) : 0.f;
    s_red[tid] = ev;
    __syncthreads();
#pragma unroll
    for (int off = 128; off; off >>= 1) {
        if (tid < off) s_red[tid] += s_red[tid + off];
        __syncthreads();
    }
    float Z = s_red[0];
    __syncthreads();
    s_p[tid] = ev / Z;
    __syncthreads();

    {
        int c = tid >> 6;
        int f = tid & 63;
        int chunk = (len + 3) >> 2;
        int n0 = c * chunk;
        int n1 = min(len, n0 + chunk);
        float acc = 0.f;
        for (int n = n0; n < n1; n++)
            acc = fmaf(s_p[n], hb[n * EMBED + f], acc);
        s_red[tid] = acc;
    }
    __syncthreads();
    if (tid < EMBED)
        s_hbar[tid] = ((s_red[tid] + s_red[64 + tid]) +
                       (s_red[128 + tid] + s_red[192 + tid]));
    __syncthreads();

    if (tid < EMBED) {
        const float* wr = W + tid * EMBED;
        float a0 = 0.f, a1 = 0.f, a2 = 0.f, a3 = 0.f;
#pragma unroll
        for (int j = 0; j < EMBED; j += 4) {
            a0 = fmaf(wr[j + 0], s_hbar[j + 0], a0);
            a1 = fmaf(wr[j + 1], s_hbar[j + 1], a1);
            a2 = fmaf(wr[j + 2], s_hbar[j + 2], a2);
            a3 = fmaf(wr[j + 3], s_hbar[j + 3], a3);
        }
        g_whbar[b * EMBED + tid] = (a0 + a1) + (a2 + a3);
    }
}

// ---------------------------------------------------------------------------
// main: grid (40, BATCH), 512 threads (16 warps). fp16 splits:
//   logits 3-product (Ehi.Hhi + Ehi.Hlo + Elo.Hhi) = 12 MMAs
//   scores 1-product (Ehi.Whi)                     =  4 MMAs
// 16 MMAs/n-tile; only 3 B tiles loaded per n-tile.
// ---------------------------------------------------------------------------
__global__ __launch_bounds__(512, 1)
void main_kernel(const float* __restrict__ E,
                 const int* __restrict__ lens,
                 const float* __restrict__ bias,
                 float* __restrict__ out) {
    extern __shared__ char smem[];
    int tid = threadIdx.x;
    int b = blockIdx.y;
    int i0 = blockIdx.x * TILE_M;
    int len = lens[b];

    // stage B tiles (contiguous copy, 86400 B)
    {
        const float4* src = (const float4*)(g_split[b]);
        float4* dst = (float4*)(smem + SM_B);
        for (int k = tid; k < B_BYTES / 16; k += 512) dst[k] = src[k];
    }
    // stage E tile as fp16 hi/lo with ROWB stride
    for (int idx = tid; idx < TILE_M * EMBED; idx += 512) {
        int m = idx >> 6;
        int f = idx & 63;
        int i = i0 + m;
        float v = (i < NUM_ITEMS) ? E[(size_t)i * EMBED + f] : 0.f;
        __half hi = __float2half_rn(v);
        __half lo = __float2half_rn(v - __half2float(hi));
        *(__half*)(smem + m * ROWB + f * 2) = hi;
        *(__half*)(smem + SM_ELO + m * ROWB + f * 2) = lo;
    }
    __syncthreads();

    int wid = tid >> 5;
    int lane = tid & 31;
    int gr = lane >> 2;     // 0..7
    int tc = lane & 3;      // 0..3
    int mbase = wid * 16;

    // preload A fragments (E_hi, E_lo), 4 k-steps x 4 regs each
    uint32_t aHi[4][4], aLo[4][4];
#pragma unroll
    for (int ks = 0; ks < 4; ks++) {
        int o = (mbase + gr) * ROWB + tc * 4 + ks * 32;
        aHi[ks][0] = *(const uint32_t*)(smem + o);
        aHi[ks][1] = *(const uint32_t*)(smem + o + 8 * ROWB);
        aHi[ks][2] = *(const uint32_t*)(smem + o + 16);
        aHi[ks][3] = *(const uint32_t*)(smem + o + 8 * ROWB + 16);
        aLo[ks][0] = *(const uint32_t*)(smem + SM_ELO + o);
        aLo[ks][1] = *(const uint32_t*)(smem + SM_ELO + o + 8 * ROWB);
        aLo[ks][2] = *(const uint32_t*)(smem + SM_ELO + o + 16);
        aLo[ks][3] = *(const uint32_t*)(smem + SM_ELO + o + 8 * ROWB + 16);
    }

    const char* Bh  = smem + SM_B;                 // h_hi
    const char* Bhl = Bh + BT_BYTES;               // h_lo
    const char* Bw  = Bh + 2 * BT_BYTES;           // wh_hi

    float Z0 = 0.f, Z1 = 0.f, A0 = 0.f, A1 = 0.f;  // rows gr, gr+8
    int nt = (len + 7) >> 3;

    for (int t = 0; t < nt; t++) {
        int rowb = (t * 8 + gr) * ROWB + tc * 4;
        uint32_t bH[4][2], bHl[4][2], bW[4][2];
#pragma unroll
        for (int ks = 0; ks < 4; ks++) {
            int o = rowb + ks * 32;
            bH[ks][0]  = *(const uint32_t*)(Bh + o);
            bH[ks][1]  = *(const uint32_t*)(Bh + o + 16);
            bHl[ks][0] = *(const uint32_t*)(Bhl + o);
            bHl[ks][1] = *(const uint32_t*)(Bhl + o + 16);
            bW[ks][0]  = *(const uint32_t*)(Bw + o);
            bW[ks][1]  = *(const uint32_t*)(Bw + o + 16);
        }
        float dA[4] = {0.f, 0.f, 0.f, 0.f};
        float dS[4] = {0.f, 0.f, 0.f, 0.f};
        // logits: 3-product fp16
#pragma unroll
        for (int ks = 0; ks < 4; ks++) MMA16816(dA, aHi[ks], bH[ks]);
#pragma unroll
        for (int ks = 0; ks < 4; ks++) MMA16816(dA, aHi[ks], bHl[ks]);
#pragma unroll
        for (int ks = 0; ks < 4; ks++) MMA16816(dA, aLo[ks], bH[ks]);
        // scores: 1-product fp16 (~2e-4 norm rel err total)
#pragma unroll
        for (int ks = 0; ks < 4; ks++) MMA16816(dS, aHi[ks], bW[ks]);

        int n0 = t * 8 + tc * 2;
        int n1 = n0 + 1;
        {
            float a = dA[0], s = dS[0];
            float l = fmaxf(a, LEAKY * a);
            float tt = (n0 < len) ? __expf(fmaxf(l - SHIFT, -80.f)) : 0.f;
            Z0 += tt; A0 = fmaf(tt, s, A0);
        }
        {
            float a = dA[1], s = dS[1];
            float l = fmaxf(a, LEAKY * a);
            float tt = (n1 < len) ? __expf(fmaxf(l - SHIFT, -80.f)) : 0.f;
            Z0 += tt; A0 = fmaf(tt, s, A0);
        }
        {
            float a = dA[2], s = dS[2];
            float l = fmaxf(a, LEAKY * a);
            float tt = (n0 < len) ? __expf(fmaxf(l - SHIFT, -80.f)) : 0.f;
            Z1 += tt; A1 = fmaf(tt, s, A1);
        }
        {
            float a = dA[3], s = dS[3];
            float l = fmaxf(a, LEAKY * a);
            float tt = (n1 < len) ? __expf(fmaxf(l - SHIFT, -80.f)) : 0.f;
            Z1 += tt; A1 = fmaf(tt, s, A1);
        }
    }

    // reduce across the 4 lanes of each row group (lane = gr*4 + tc)
    Z0 += __shfl_xor_sync(0xffffffffu, Z0, 1);
    Z0 += __shfl_xor_sync(0xffffffffu, Z0, 2);
    A0 += __shfl_xor_sync(0xffffffffu, A0, 1);
    A0 += __shfl_xor_sync(0xffffffffu, A0, 2);
    Z1 += __shfl_xor_sync(0xffffffffu, Z1, 1);
    Z1 += __shfl_xor_sync(0xffffffffu, Z1, 2);
    A1 += __shfl_xor_sync(0xffffffffu, A1, 1);
    A1 += __shfl_xor_sync(0xffffffffu, A1, 2);

    if (tc == 0) {
#pragma unroll
        for (int half = 0; half < 2; half++) {
            int i = i0 + mbase + gr + half * 8;
            if (i < NUM_ITEMS) {
                const float4* er = (const float4*)(E + (size_t)i * EMBED);
                const float4* wr = (const float4*)(g_whbar + b * EMBED);
                const float4* br = (const float4*)bias;
                float ub = 0.f, cb = 0.f;
#pragma unroll
                for (int k = 0; k < 16; k++) {
                    float4 e = er[k], w = wr[k], bv = br[k];
                    ub = fmaf(e.x, w.x, ub); ub = fmaf(e.y, w.y, ub);
                    ub = fmaf(e.z, w.z, ub); ub = fmaf(e.w, w.w, ub);
                    cb = fmaf(e.x, bv.x, cb); cb = fmaf(e.y, bv.y, cb);
                    cb = fmaf(e.z, bv.z, cb); cb = fmaf(e.w, bv.w, cb);
                }
                float Z = half ? Z1 : Z0;
                float A = half ? A1 : A0;
                out[b * NUM_ITEMS + i] = 0.5f * (A / Z) + 0.5f * ub + cb;
            }
        }
    }
}

// ---------------------------------------------------------------------------
extern "C" void kernel_launch(void* const* d_in, const int* in_sizes, int n_in,
                              void* d_out, int out_size) {
    const int*   ids  = (const int*)d_in[0];    // [32,200] int32
    const int*   lens = (const int*)d_in[1];    // [32] int32
    const float* E    = (const float*)d_in[2];  // [10000,64]
    const float* U    = (const float*)d_in[3];  // [1,64]
    const float* W    = (const float*)d_in[4];  // [64,64]
    const float* bias = (const float*)d_in[5];  // [64]
    float* out = (float*)d_out;                 // [32,10000]

    prep_gather_kernel<<<dim3(MAX_HIST / GCHUNK, BATCH), 256>>>(ids, E, W);
    prep_soft_kernel<<<BATCH, 256>>>(lens, U, W);

    cudaFuncSetAttribute(main_kernel,
                         cudaFuncAttributeMaxDynamicSharedMemorySize, SM_TOTAL);
    dim3 grid((NUM_ITEMS + TILE_M - 1) / TILE_M, BATCH);
    main_kernel<<<grid, 512, SM_TOTAL>>>(E, lens, bias, out);
}